// round 4
// baseline (speedup 1.0000x reference)
#include <cuda_runtime.h>
#include <cstdint>

// ============================================================================
// y = x @ scatter(W, sel, idx)^T      (M=8192, N=4096, K=4096, f32)
//
// Harness builds with a baseline compute_103 PTX target -> tcgen05/TMEM is
// NOT assemblable. Use baseline-PTX tensor path instead:
//   prep: round x / scattered W to tf32 (cvt.rna) into device scratch
//   GEMM: Ampere-style cp.async 4-stage pipeline + mma.sync m16n8k8 tf32
//         CTA tile 128x128, BK=32, 8 warps (warp tile 64x32)
// ============================================================================

// ---------------- device-global scratch (sanctioned) ----------------
__device__ float g_X[33554432];   // 8192 x 4096 tf32-rounded
__device__ float g_W[16777216];   // 4096 x 4096 scattered + tf32-rounded
__device__ int   g_blkmap[256];   // 16x16 grid -> block id or -1

// ---------------- helpers ----------------
__device__ __forceinline__ float tf32_rn(float x) {
    uint32_t u;
    asm("cvt.rna.tf32.f32 %0, %1;" : "=r"(u) : "f"(x));
    return __uint_as_float(u);
}
__device__ __forceinline__ uint32_t smem_u32(const void* p) {
    uint32_t a;
    asm("{ .reg .u64 t; cvta.to.shared.u64 t, %1; cvt.u32.u64 %0, t; }"
        : "=r"(a) : "l"(p));
    return a;
}
#define CPA16(saddr, gptr) \
    asm volatile("cp.async.cg.shared.global [%0], [%1], 16;" \
                 :: "r"(saddr), "l"(gptr) : "memory")
#define CP_COMMIT() asm volatile("cp.async.commit_group;" ::: "memory")
#define CP_WAIT2()  asm volatile("cp.async.wait_group 2;"  ::: "memory")

// mma.sync m16n8k8 tf32 (baseline PTX, sm_80+)
__device__ __forceinline__ void mma8(float* d, const uint32_t* a, const uint32_t* b) {
    asm volatile(
        "mma.sync.aligned.m16n8k8.row.col.f32.tf32.tf32.f32 "
        "{%0,%1,%2,%3}, {%4,%5,%6,%7}, {%8,%9}, {%0,%1,%2,%3};"
        : "+f"(d[0]), "+f"(d[1]), "+f"(d[2]), "+f"(d[3])
        : "r"(a[0]), "r"(a[1]), "r"(a[2]), "r"(a[3]), "r"(b[0]), "r"(b[1]));
}

// ---------------- prep kernels ----------------

// Build 16x16 block map; auto-detect int64 vs int32 index buffer (JAX may
// silently downcast): int64 data has zero odd 32-bit words for values 0..15.
__global__ void blkmap_k(const int* __restrict__ idxw) {
    int t = threadIdx.x;
    if (t < 256) g_blkmap[t] = -1;
    __syncthreads();
    if (t == 0) {
        bool is64 = true;
        for (int i = 0; i < 32; i++)
            if (idxw[2 * i + 1] != 0) { is64 = false; break; }
        for (int b = 0; b < 32; b++) {
            int ro, ci;
            if (is64) {
                const long long* q = (const long long*)idxw;
                ro = (int)q[2 * b]; ci = (int)q[2 * b + 1];
            } else {
                ro = idxw[2 * b]; ci = idxw[2 * b + 1];
            }
            if (ro >= 0 && ro < 16 && ci >= 0 && ci < 16)
                g_blkmap[ro * 16 + ci] = b;
        }
    }
}

// Fused scatter + tf32 round of W. One float4 per thread.
__global__ void prep_w_k(const float* __restrict__ w, const float* __restrict__ sel) {
    int gi = blockIdx.x * 256 + threadIdx.x;   // float4 index 0..4194303
    int o  = gi >> 10;                         // output row (4096 wide = 1024 f4)
    int i  = (gi & 1023) << 2;                 // input col
    int blk = g_blkmap[((o >> 8) << 4) + (i >> 8)];
    float4 v;
    if (blk >= 0)
        v = *(const float4*)(sel + (((size_t)blk << 8) + (o & 255)) * 256 + (i & 255));
    else
        v = ((const float4*)w)[gi];
    v.x = tf32_rn(v.x); v.y = tf32_rn(v.y); v.z = tf32_rn(v.z); v.w = tf32_rn(v.w);
    ((float4*)g_W)[gi] = v;
}

// tf32 round of x
__global__ void prep_x_k(const float* __restrict__ x) {
    int gi = blockIdx.x * 256 + threadIdx.x;   // 0..8388607
    float4 v = ((const float4*)x)[gi];
    v.x = tf32_rn(v.x); v.y = tf32_rn(v.y); v.z = tf32_rn(v.z); v.w = tf32_rn(v.w);
    ((float4*)g_X)[gi] = v;
}

// ---------------- GEMM ----------------
// CTA 128x128, BK=32. SMEM rows padded to 36 floats -> conflict-free frags.
// Stage = (128 A-rows + 128 B-rows) * 36 floats = 36864 B; 4 stages = 147456 B.
#define LDSROW      36
#define HALF_FLOATS (128 * LDSROW)            // 4608
#define STAGE_FLOATS (2 * HALF_FLOATS)        // 9216
#define NSTAGES     4
#define SMEM_BYTES  (NSTAGES * STAGE_FLOATS * 4)   // 147456

__global__ void __launch_bounds__(256, 1)
LinearLayer_MatrixSparsity_9801115369812_kernel(float* __restrict__ out) {
    extern __shared__ float smem[];
    const uint32_t sb = smem_u32(smem);
    const int tid  = threadIdx.x;
    const int lane = tid & 31;
    const int wid  = tid >> 5;
    const int tile_n = blockIdx.x;     // 0..31
    const int tile_m = blockIdx.y;     // 0..63

    const float* ga = g_X + (size_t)(tile_m * 128) * 4096;
    const float* gb = g_W + (size_t)(tile_n * 128) * 4096;

    // ---- per-thread loader mapping (8 x 16B cp.async per stage) ----
    // v = j*256 + tid : first 1024 chunks = A (128 rows x 8), rest = B
    uint32_t s_off[8];
    const float* g_ptr[8];
    #pragma unroll
    for (int j = 0; j < 8; j++) {
        int v   = j * 256 + tid;
        int isB = v >> 10;
        int vv  = v & 1023;
        int row = vv >> 3;
        int c16 = vv & 7;
        s_off[j] = (uint32_t)(isB * (HALF_FLOATS * 4) + row * (LDSROW * 4) + c16 * 16);
        g_ptr[j] = (isB ? gb : ga) + (size_t)row * 4096 + c16 * 4;
    }

    #define LOAD_STAGE(s, kc) do {                                            \
        const uint32_t _st = sb + (s) * (STAGE_FLOATS * 4);                   \
        const int _k0 = (kc) * 32;                                            \
        _Pragma("unroll")                                                     \
        for (int j = 0; j < 8; j++) CPA16(_st + s_off[j], g_ptr[j] + _k0);    \
    } while (0)

    // ---- prologue: 3 stages in flight ----
    LOAD_STAGE(0, 0); CP_COMMIT();
    LOAD_STAGE(1, 1); CP_COMMIT();
    LOAD_STAGE(2, 2); CP_COMMIT();

    const int warp_m = (wid >> 2) * 64;    // 0 / 64
    const int warp_n = (wid & 3) * 32;     // 0..96
    const int qid = lane & 3;              // k offset within fragment
    const int gid = lane >> 2;             // row-group within fragment

    float acc[4][4][4];
    #pragma unroll
    for (int mi = 0; mi < 4; mi++)
        #pragma unroll
        for (int ni = 0; ni < 4; ni++)
            #pragma unroll
            for (int q = 0; q < 4; q++) acc[mi][ni][q] = 0.0f;

    for (int kc = 0; kc < 128; kc++) {
        CP_WAIT2();
        __syncthreads();
        if (kc + 3 < 128) LOAD_STAGE((kc + 3) & 3, kc + 3);
        CP_COMMIT();

        const float* As = smem + (kc & 3) * STAGE_FLOATS;
        const float* Bs = As + HALF_FLOATS;
        #pragma unroll
        for (int ks = 0; ks < 4; ks++) {
            const int k = ks * 8;
            uint32_t af[4][4], bf[4][2];
            #pragma unroll
            for (int mi = 0; mi < 4; mi++) {
                const float* ap = As + (warp_m + mi * 16 + gid) * LDSROW + k + qid;
                af[mi][0] = __float_as_uint(ap[0]);
                af[mi][1] = __float_as_uint(ap[8 * LDSROW]);
                af[mi][2] = __float_as_uint(ap[4]);
                af[mi][3] = __float_as_uint(ap[8 * LDSROW + 4]);
            }
            #pragma unroll
            for (int ni = 0; ni < 4; ni++) {
                const float* bp = Bs + (warp_n + ni * 8 + gid) * LDSROW + k + qid;
                bf[ni][0] = __float_as_uint(bp[0]);
                bf[ni][1] = __float_as_uint(bp[4]);
            }
            #pragma unroll
            for (int mi = 0; mi < 4; mi++)
                #pragma unroll
                for (int ni = 0; ni < 4; ni++)
                    mma8(acc[mi][ni], af[mi], bf[ni]);
        }
        __syncthreads();
    }

    // ---- epilogue: direct f32 stores (32B-sector complete per quad) ----
    #pragma unroll
    for (int mi = 0; mi < 4; mi++) {
        #pragma unroll
        for (int ni = 0; ni < 4; ni++) {
            const size_t r0 = (size_t)(tile_m * 128 + warp_m + mi * 16 + gid);
            const int    c  = tile_n * 128 + warp_n + ni * 8 + qid * 2;
            *(float2*)(out + r0 * 4096 + c) =
                make_float2(acc[mi][ni][0], acc[mi][ni][1]);
            *(float2*)(out + (r0 + 8) * 4096 + c) =
                make_float2(acc[mi][ni][2], acc[mi][ni][3]);
        }
    }
}

// ---------------- launch ----------------
extern "C" void kernel_launch(void* const* d_in, const int* in_sizes, int n_in,
                              void* d_out, int out_size) {
    const float* x   = nullptr;
    const float* sel = nullptr;
    const float* w   = nullptr;
    const int*   idx = nullptr;
    for (int i = 0; i < n_in; i++) {
        switch (in_sizes[i]) {
            case 33554432: x   = (const float*)d_in[i]; break;
            case 16777216: w   = (const float*)d_in[i]; break;
            case 2097152:  sel = (const float*)d_in[i]; break;
            default:       idx = (const int*)d_in[i];   break;
        }
    }
    if (!x)   x   = (const float*)d_in[0];
    if (!sel) sel = (const float*)d_in[1];
    if (!w)   w   = (const float*)d_in[2];
    if (!idx) idx = (const int*)d_in[3];

    cudaFuncSetAttribute(LinearLayer_MatrixSparsity_9801115369812_kernel,
                         cudaFuncAttributeMaxDynamicSharedMemorySize, SMEM_BYTES);

    blkmap_k<<<1, 256>>>(idx);
    prep_w_k<<<16384, 256>>>(w, sel);
    prep_x_k<<<32768, 256>>>(x);
    LinearLayer_MatrixSparsity_9801115369812_kernel
        <<<dim3(32, 64), 256, SMEM_BYTES>>>((float*)d_out);
}

// round 5
// speedup vs baseline: 1.1463x; 1.1463x over previous
#include <cuda_runtime.h>
#include <cstdint>

// ============================================================================
// y = x @ scatter(W, sel, idx)^T      (M=8192, N=4096, K=4096, f32)
//
// Baseline-PTX tensor path (tcgen05 not assemblable under compute_103):
//   prep: round x / scattered W to tf32 (cvt.rna) into device scratch
//   GEMM: cp.async 3-stage pipeline + mma.sync m16n8k8 tf32
//         CTA tile 128x128, BK=32, 8 warps (warp tile 64x32)
//         __launch_bounds__(256, 2)  -> 2 CTAs/SM (16 warps) for latency hiding
//         single __syncthreads per k-chunk (CUTLASS multistage ordering)
// ============================================================================

// ---------------- device-global scratch (sanctioned) ----------------
__device__ float g_X[33554432];   // 8192 x 4096 tf32-rounded
__device__ float g_W[16777216];   // 4096 x 4096 scattered + tf32-rounded
__device__ int   g_blkmap[256];   // 16x16 grid -> block id or -1

// ---------------- helpers ----------------
__device__ __forceinline__ float tf32_rn(float x) {
    uint32_t u;
    asm("cvt.rna.tf32.f32 %0, %1;" : "=r"(u) : "f"(x));
    return __uint_as_float(u);
}
__device__ __forceinline__ uint32_t smem_u32(const void* p) {
    uint32_t a;
    asm("{ .reg .u64 t; cvta.to.shared.u64 t, %1; cvt.u32.u64 %0, t; }"
        : "=r"(a) : "l"(p));
    return a;
}
#define CPA16(saddr, gptr) \
    asm volatile("cp.async.cg.shared.global [%0], [%1], 16;" \
                 :: "r"(saddr), "l"(gptr) : "memory")
#define CP_COMMIT() asm volatile("cp.async.commit_group;" ::: "memory")
#define CP_WAIT1()  asm volatile("cp.async.wait_group 1;"  ::: "memory")

// mma.sync m16n8k8 tf32 (baseline PTX, sm_80+)
__device__ __forceinline__ void mma8(float* d, const uint32_t* a, const uint32_t* b) {
    asm volatile(
        "mma.sync.aligned.m16n8k8.row.col.f32.tf32.tf32.f32 "
        "{%0,%1,%2,%3}, {%4,%5,%6,%7}, {%8,%9}, {%0,%1,%2,%3};"
        : "+f"(d[0]), "+f"(d[1]), "+f"(d[2]), "+f"(d[3])
        : "r"(a[0]), "r"(a[1]), "r"(a[2]), "r"(a[3]), "r"(b[0]), "r"(b[1]));
}

// ---------------- prep kernels ----------------

__global__ void blkmap_k(const int* __restrict__ idxw) {
    int t = threadIdx.x;
    if (t < 256) g_blkmap[t] = -1;
    __syncthreads();
    if (t == 0) {
        bool is64 = true;
        for (int i = 0; i < 32; i++)
            if (idxw[2 * i + 1] != 0) { is64 = false; break; }
        for (int b = 0; b < 32; b++) {
            int ro, ci;
            if (is64) {
                const long long* q = (const long long*)idxw;
                ro = (int)q[2 * b]; ci = (int)q[2 * b + 1];
            } else {
                ro = idxw[2 * b]; ci = idxw[2 * b + 1];
            }
            if (ro >= 0 && ro < 16 && ci >= 0 && ci < 16)
                g_blkmap[ro * 16 + ci] = b;
        }
    }
}

__global__ void prep_w_k(const float* __restrict__ w, const float* __restrict__ sel) {
    int gi = blockIdx.x * 256 + threadIdx.x;   // float4 index 0..4194303
    int o  = gi >> 10;
    int i  = (gi & 1023) << 2;
    int blk = g_blkmap[((o >> 8) << 4) + (i >> 8)];
    float4 v;
    if (blk >= 0)
        v = *(const float4*)(sel + (((size_t)blk << 8) + (o & 255)) * 256 + (i & 255));
    else
        v = ((const float4*)w)[gi];
    v.x = tf32_rn(v.x); v.y = tf32_rn(v.y); v.z = tf32_rn(v.z); v.w = tf32_rn(v.w);
    ((float4*)g_W)[gi] = v;
}

__global__ void prep_x_k(const float* __restrict__ x) {
    int gi = blockIdx.x * 256 + threadIdx.x;   // 0..8388607
    float4 v = ((const float4*)x)[gi];
    v.x = tf32_rn(v.x); v.y = tf32_rn(v.y); v.z = tf32_rn(v.z); v.w = tf32_rn(v.w);
    ((float4*)g_X)[gi] = v;
}

// ---------------- GEMM ----------------
// CTA 128x128, BK=32. SMEM rows padded to 36 floats (conflict-free frags).
// Stage = (128 A + 128 B rows) * 36 floats * 4B = 36864 B; 3 stages = 110592 B.
// Two CTAs per SM: 2 * 110592 = 221184 B < 228KB carveout; 128 regs * 512 thr.
#define LDSROW       36
#define HALF_FLOATS  (128 * LDSROW)            // 4608
#define STAGE_FLOATS (2 * HALF_FLOATS)         // 9216
#define NSTAGES      3
#define SMEM_BYTES   (NSTAGES * STAGE_FLOATS * 4)   // 110592

__global__ void __launch_bounds__(256, 2)
LinearLayer_MatrixSparsity_9801115369812_kernel(float* __restrict__ out) {
    extern __shared__ float smem[];
    const uint32_t sb = smem_u32(smem);
    const int tid  = threadIdx.x;
    const int lane = tid & 31;
    const int wid  = tid >> 5;
    const int tile_n = blockIdx.x;     // 0..31
    const int tile_m = blockIdx.y;     // 0..63

    // Loader mapping: thread handles row (tid>>3)+{0,32,64,96}, 16B chunk tid&7,
    // for both A (g_X) and B (g_W). Bases only — offsets are immediates.
    const float* ga = g_X + (size_t)(tile_m * 128 + (tid >> 3)) * 4096 + (tid & 7) * 4;
    const float* gb = g_W + (size_t)(tile_n * 128 + (tid >> 3)) * 4096 + (tid & 7) * 4;
    const uint32_t soA = sb + (uint32_t)((tid >> 3) * (LDSROW * 4) + (tid & 7) * 16);
    const uint32_t soB = soA + HALF_FLOATS * 4;

    #define LOAD_STAGE(s, kc) do {                                               \
        const uint32_t _d = (uint32_t)(s) * (STAGE_FLOATS * 4);                  \
        const int _k = (kc) * 32;                                                \
        _Pragma("unroll")                                                        \
        for (int j = 0; j < 4; j++) {                                            \
            CPA16(soA + _d + j * (32 * LDSROW * 4), ga + (size_t)j * (32 * 4096) + _k); \
            CPA16(soB + _d + j * (32 * LDSROW * 4), gb + (size_t)j * (32 * 4096) + _k); \
        }                                                                        \
    } while (0)

    // prologue: 2 chunks in flight
    LOAD_STAGE(0, 0); CP_COMMIT();
    LOAD_STAGE(1, 1); CP_COMMIT();

    const int warp_m = (wid >> 2) * 64;    // 0 / 64
    const int warp_n = (wid & 3) * 32;     // 0..96
    const int qid = lane & 3;
    const int gid = lane >> 2;

    float acc[4][4][4];
    #pragma unroll
    for (int mi = 0; mi < 4; mi++)
        #pragma unroll
        for (int ni = 0; ni < 4; ni++)
            #pragma unroll
            for (int q = 0; q < 4; q++) acc[mi][ni][q] = 0.0f;

    int cs = 0, ls = 2;   // compute stage, load stage
    for (int kc = 0; kc < 128; kc++) {
        CP_WAIT1();
        __syncthreads();
        // fill stage ls (== stage fully consumed in iter kc-1) with chunk kc+2
        if (kc + 2 < 128) LOAD_STAGE(ls, kc + 2);
        CP_COMMIT();

        const float* As = smem + cs * STAGE_FLOATS;
        const float* Bs = As + HALF_FLOATS;
        #pragma unroll
        for (int ks = 0; ks < 4; ks++) {
            const int k = ks * 8;
            uint32_t af[4][4], bf[4][2];
            #pragma unroll
            for (int mi = 0; mi < 4; mi++) {
                const float* ap = As + (warp_m + mi * 16 + gid) * LDSROW + k + qid;
                af[mi][0] = __float_as_uint(ap[0]);
                af[mi][1] = __float_as_uint(ap[8 * LDSROW]);
                af[mi][2] = __float_as_uint(ap[4]);
                af[mi][3] = __float_as_uint(ap[8 * LDSROW + 4]);
            }
            #pragma unroll
            for (int ni = 0; ni < 4; ni++) {
                const float* bp = Bs + (warp_n + ni * 8 + gid) * LDSROW + k + qid;
                bf[ni][0] = __float_as_uint(bp[0]);
                bf[ni][1] = __float_as_uint(bp[4]);
            }
            #pragma unroll
            for (int mi = 0; mi < 4; mi++)
                #pragma unroll
                for (int ni = 0; ni < 4; ni++)
                    mma8(acc[mi][ni], af[mi], bf[ni]);
        }
        cs = (cs == NSTAGES - 1) ? 0 : cs + 1;
        ls = (ls == NSTAGES - 1) ? 0 : ls + 1;
    }

    // ---- epilogue: direct f32 stores ----
    #pragma unroll
    for (int mi = 0; mi < 4; mi++) {
        #pragma unroll
        for (int ni = 0; ni < 4; ni++) {
            const size_t r0 = (size_t)(tile_m * 128 + warp_m + mi * 16 + gid);
            const int    c  = tile_n * 128 + warp_n + ni * 8 + qid * 2;
            *(float2*)(out + r0 * 4096 + c) =
                make_float2(acc[mi][ni][0], acc[mi][ni][1]);
            *(float2*)(out + (r0 + 8) * 4096 + c) =
                make_float2(acc[mi][ni][2], acc[mi][ni][3]);
        }
    }
}

// ---------------- launch ----------------
extern "C" void kernel_launch(void* const* d_in, const int* in_sizes, int n_in,
                              void* d_out, int out_size) {
    const float* x   = nullptr;
    const float* sel = nullptr;
    const float* w   = nullptr;
    const int*   idx = nullptr;
    for (int i = 0; i < n_in; i++) {
        switch (in_sizes[i]) {
            case 33554432: x   = (const float*)d_in[i]; break;
            case 16777216: w   = (const float*)d_in[i]; break;
            case 2097152:  sel = (const float*)d_in[i]; break;
            default:       idx = (const int*)d_in[i];   break;
        }
    }
    if (!x)   x   = (const float*)d_in[0];
    if (!sel) sel = (const float*)d_in[1];
    if (!w)   w   = (const float*)d_in[2];
    if (!idx) idx = (const int*)d_in[3];

    cudaFuncSetAttribute(LinearLayer_MatrixSparsity_9801115369812_kernel,
                         cudaFuncAttributeMaxDynamicSharedMemorySize, SMEM_BYTES);

    blkmap_k<<<1, 256>>>(idx);
    prep_w_k<<<16384, 256>>>(w, sel);
    prep_x_k<<<32768, 256>>>(x);
    LinearLayer_MatrixSparsity_9801115369812_kernel
        <<<dim3(32, 64), 256, SMEM_BYTES>>>((float*)d_out);
}

// round 6
// speedup vs baseline: 1.2383x; 1.0803x over previous
#include <cuda_runtime.h>
#include <cstdint>

// ============================================================================
// y = x @ scatter(W, sel, idx)^T      (M=8192, N=4096, K=4096, f32)
//
// Baseline-PTX tensor path (tcgen05 not available under compute_103):
//   prep: round x / scattered W to tf32 (cvt.rna) into device scratch
//   GEMM: cp.async 3-stage pipeline + mma.sync m16n8k8 tf32
//         CTA 128x128, BK=32, 4 warps (warp tile 64x64, 2x2 grid)
//         ldmatrix.x4 fragment loads, __launch_bounds__(128,2) -> 256 reg/thr
// ============================================================================

// ---------------- device-global scratch (sanctioned) ----------------
__device__ float g_X[33554432];   // 8192 x 4096 tf32-rounded
__device__ float g_W[16777216];   // 4096 x 4096 scattered + tf32-rounded
__device__ int   g_blkmap[256];   // 16x16 grid -> block id or -1

// ---------------- helpers ----------------
__device__ __forceinline__ float tf32_rn(float x) {
    uint32_t u;
    asm("cvt.rna.tf32.f32 %0, %1;" : "=r"(u) : "f"(x));
    return __uint_as_float(u);
}
__device__ __forceinline__ uint32_t smem_u32(const void* p) {
    uint32_t a;
    asm("{ .reg .u64 t; cvta.to.shared.u64 t, %1; cvt.u32.u64 %0, t; }"
        : "=r"(a) : "l"(p));
    return a;
}
#define CPA16(saddr, gptr) \
    asm volatile("cp.async.cg.shared.global [%0], [%1], 16;" \
                 :: "r"(saddr), "l"(gptr) : "memory")
#define CP_COMMIT() asm volatile("cp.async.commit_group;" ::: "memory")
#define CP_WAIT1()  asm volatile("cp.async.wait_group 1;"  ::: "memory")

// ldmatrix x4: four 8x8 b16 matrices == four 8x4 tf32 tiles
#define LDSM4(r0, r1, r2, r3, addr) \
    asm volatile("ldmatrix.sync.aligned.m8n8.x4.shared.b16 {%0,%1,%2,%3}, [%4];" \
                 : "=r"(r0), "=r"(r1), "=r"(r2), "=r"(r3) : "r"(addr))

// mma.sync m16n8k8 tf32
__device__ __forceinline__ void mma8(float* d, const uint32_t* a, const uint32_t* b) {
    asm volatile(
        "mma.sync.aligned.m16n8k8.row.col.f32.tf32.tf32.f32 "
        "{%0,%1,%2,%3}, {%4,%5,%6,%7}, {%8,%9}, {%0,%1,%2,%3};"
        : "+f"(d[0]), "+f"(d[1]), "+f"(d[2]), "+f"(d[3])
        : "r"(a[0]), "r"(a[1]), "r"(a[2]), "r"(a[3]), "r"(b[0]), "r"(b[1]));
}

// ---------------- prep kernels ----------------

__global__ void blkmap_k(const int* __restrict__ idxw) {
    int t = threadIdx.x;
    if (t < 256) g_blkmap[t] = -1;
    __syncthreads();
    if (t == 0) {
        bool is64 = true;
        for (int i = 0; i < 32; i++)
            if (idxw[2 * i + 1] != 0) { is64 = false; break; }
        for (int b = 0; b < 32; b++) {
            int ro, ci;
            if (is64) {
                const long long* q = (const long long*)idxw;
                ro = (int)q[2 * b]; ci = (int)q[2 * b + 1];
            } else {
                ro = idxw[2 * b]; ci = idxw[2 * b + 1];
            }
            if (ro >= 0 && ro < 16 && ci >= 0 && ci < 16)
                g_blkmap[ro * 16 + ci] = b;
        }
    }
}

__global__ void prep_w_k(const float* __restrict__ w, const float* __restrict__ sel) {
    int gi = blockIdx.x * 256 + threadIdx.x;   // float4 index 0..4194303
    int o  = gi >> 10;
    int i  = (gi & 1023) << 2;
    int blk = g_blkmap[((o >> 8) << 4) + (i >> 8)];
    float4 v;
    if (blk >= 0)
        v = *(const float4*)(sel + (((size_t)blk << 8) + (o & 255)) * 256 + (i & 255));
    else
        v = ((const float4*)w)[gi];
    v.x = tf32_rn(v.x); v.y = tf32_rn(v.y); v.z = tf32_rn(v.z); v.w = tf32_rn(v.w);
    ((float4*)g_W)[gi] = v;
}

__global__ void prep_x_k(const float* __restrict__ x) {
    int gi = blockIdx.x * 256 + threadIdx.x;   // 0..8388607
    float4 v = ((const float4*)x)[gi];
    v.x = tf32_rn(v.x); v.y = tf32_rn(v.y); v.z = tf32_rn(v.z); v.w = tf32_rn(v.w);
    ((float4*)g_X)[gi] = v;
}

// ---------------- GEMM ----------------
// CTA 128x128, BK=32, 4 warps (warp tile 64x64). SMEM rows = 36 floats (144B):
// LDSM 8-row banks distinct (9r mod 8), cp.async chunks uniform over quads.
// Stage = 2 * 128 * 144 = 36864 B; 3 stages = 110592 B; 2 CTAs/SM = 221184 B.
#define LDSROW       36
#define HALF_BYTES   (128 * LDSROW * 4)        // 18432
#define STAGE_BYTES_ (2 * HALF_BYTES)          // 36864
#define NSTAGES      3
#define SMEM_BYTES   (NSTAGES * STAGE_BYTES_)  // 110592

__global__ void __launch_bounds__(128, 2)
LinearLayer_MatrixSparsity_9801115369812_kernel(float* __restrict__ out) {
    extern __shared__ float smem[];
    const uint32_t sb = smem_u32(smem);
    const int tid  = threadIdx.x;
    const int lane = tid & 31;
    const int wid  = tid >> 5;           // 0..3
    const int tile_n = blockIdx.x;       // 0..31
    const int tile_m = blockIdx.y;       // 0..63

    // ---- loader mapping: 16 rows per thread-group, 16B chunk = tid&7 ----
    const float* ga = g_X + (size_t)(tile_m * 128 + (tid >> 3)) * 4096 + (tid & 7) * 4;
    const float* gb = g_W + (size_t)(tile_n * 128 + (tid >> 3)) * 4096 + (tid & 7) * 4;
    const uint32_t soA = sb + (uint32_t)((tid >> 3) * (LDSROW * 4) + (tid & 7) * 16);
    const uint32_t soB = soA + HALF_BYTES;

    #define LOAD_STAGE(s, kc) do {                                                    \
        const uint32_t _d = (uint32_t)(s) * STAGE_BYTES_;                             \
        const int _k = (kc) * 32;                                                     \
        _Pragma("unroll")                                                             \
        for (int j = 0; j < 8; j++) {                                                 \
            CPA16(soA + _d + j * (16 * LDSROW * 4), ga + (size_t)j * (16 * 4096) + _k); \
            CPA16(soB + _d + j * (16 * LDSROW * 4), gb + (size_t)j * (16 * 4096) + _k); \
        }                                                                             \
    } while (0)

    LOAD_STAGE(0, 0); CP_COMMIT();
    LOAD_STAGE(1, 1); CP_COMMIT();

    const int warp_m = (wid >> 1) * 64;
    const int warp_n = (wid & 1) * 64;

    // ldmatrix per-thread offsets (within a stage)
    // A (mi tile 16x8): t0-7 m0 rows, t8-15 m1 rows(+8), t16-23 m2 (col+4), t24-31 m3
    uint32_t aoff[4], boff[4];
    {
        const int r8a = (lane >> 3) & 1, c4a = (lane >> 4) & 1;
        #pragma unroll
        for (int mi = 0; mi < 4; mi++)
            aoff[mi] = (uint32_t)((warp_m + mi * 16 + (lane & 7) + r8a * 8) * (LDSROW * 4)
                                  + c4a * 16);
        // B (nj pair of 8-wide tiles): t8-15 -> col+4, t16-31 -> row+8
        const int r8b = (lane >> 4) & 1, c4b = (lane >> 3) & 1;
        #pragma unroll
        for (int nj = 0; nj < 4; nj++)
            boff[nj] = (uint32_t)(HALF_BYTES
                                  + (warp_n + nj * 16 + (lane & 7) + r8b * 8) * (LDSROW * 4)
                                  + c4b * 16);
    }

    float acc[4][8][4];
    #pragma unroll
    for (int mi = 0; mi < 4; mi++)
        #pragma unroll
        for (int ni = 0; ni < 8; ni++)
            #pragma unroll
            for (int q = 0; q < 4; q++) acc[mi][ni][q] = 0.0f;

    int cs = 0, ls = 2;
    for (int kc = 0; kc < 128; kc++) {
        CP_WAIT1();
        __syncthreads();
        if (kc + 2 < 128) LOAD_STAGE(ls, kc + 2);
        CP_COMMIT();

        const uint32_t sbase = sb + (uint32_t)cs * STAGE_BYTES_;
        #pragma unroll
        for (int ks = 0; ks < 4; ks++) {
            const uint32_t koff = (uint32_t)(ks * 32);
            uint32_t af[4][4], bf[4][4];
            #pragma unroll
            for (int mi = 0; mi < 4; mi++)
                LDSM4(af[mi][0], af[mi][1], af[mi][2], af[mi][3],
                      sbase + aoff[mi] + koff);
            #pragma unroll
            for (int nj = 0; nj < 4; nj++)
                LDSM4(bf[nj][0], bf[nj][1], bf[nj][2], bf[nj][3],
                      sbase + boff[nj] + koff);
            #pragma unroll
            for (int mi = 0; mi < 4; mi++)
                #pragma unroll
                for (int ni = 0; ni < 8; ni++)
                    mma8(acc[mi][ni], af[mi], &bf[ni >> 1][(ni & 1) * 2]);
        }
        cs = (cs == NSTAGES - 1) ? 0 : cs + 1;
        ls = (ls == NSTAGES - 1) ? 0 : ls + 1;
    }

    // ---- epilogue ----
    const int qid = lane & 3;
    const int gid = lane >> 2;
    #pragma unroll
    for (int mi = 0; mi < 4; mi++) {
        #pragma unroll
        for (int ni = 0; ni < 8; ni++) {
            const size_t r0 = (size_t)(tile_m * 128 + warp_m + mi * 16 + gid);
            const int    c  = tile_n * 128 + warp_n + ni * 8 + qid * 2;
            *(float2*)(out + r0 * 4096 + c) =
                make_float2(acc[mi][ni][0], acc[mi][ni][1]);
            *(float2*)(out + (r0 + 8) * 4096 + c) =
                make_float2(acc[mi][ni][2], acc[mi][ni][3]);
        }
    }
}

// ---------------- launch ----------------
extern "C" void kernel_launch(void* const* d_in, const int* in_sizes, int n_in,
                              void* d_out, int out_size) {
    const float* x   = nullptr;
    const float* sel = nullptr;
    const float* w   = nullptr;
    const int*   idx = nullptr;
    for (int i = 0; i < n_in; i++) {
        switch (in_sizes[i]) {
            case 33554432: x   = (const float*)d_in[i]; break;
            case 16777216: w   = (const float*)d_in[i]; break;
            case 2097152:  sel = (const float*)d_in[i]; break;
            default:       idx = (const int*)d_in[i];   break;
        }
    }
    if (!x)   x   = (const float*)d_in[0];
    if (!sel) sel = (const float*)d_in[1];
    if (!w)   w   = (const float*)d_in[2];
    if (!idx) idx = (const int*)d_in[3];

    cudaFuncSetAttribute(LinearLayer_MatrixSparsity_9801115369812_kernel,
                         cudaFuncAttributeMaxDynamicSharedMemorySize, SMEM_BYTES);

    blkmap_k<<<1, 256>>>(idx);
    prep_w_k<<<16384, 256>>>(w, sel);
    prep_x_k<<<32768, 256>>>(x);
    LinearLayer_MatrixSparsity_9801115369812_kernel
        <<<dim3(32, 64), 128, SMEM_BYTES>>>((float*)d_out);
}

// round 7
// speedup vs baseline: 1.6474x; 1.3303x over previous
#include <cuda_runtime.h>
#include <cstdint>

// ============================================================================
// y = x @ scatter(W, sel, idx)^T      (M=8192, N=4096, K=4096, f32)
//
// Baseline-PTX tensor path (tcgen05 not available under compute_103):
//   prep: round x / scattered W to tf32 (cvt.rna) into device scratch
//   GEMM: cp.async 3-stage pipeline + mma.sync m16n8k8 tf32
//         CTA 128x128, BK=32, 4 warps (warp tile 64x64), 2 CTAs/SM
//         ks-level software pipeline: LDSM(ks+1) issued BEFORE mma(ks)
//         (double-buffered fragments), cp.async spread into the mma stream
// ============================================================================

// ---------------- device-global scratch (sanctioned) ----------------
__device__ float g_X[33554432];   // 8192 x 4096 tf32-rounded
__device__ float g_W[16777216];   // 4096 x 4096 scattered + tf32-rounded
__device__ int   g_blkmap[256];   // 16x16 grid -> block id or -1

// ---------------- helpers ----------------
__device__ __forceinline__ float tf32_rn(float x) {
    uint32_t u;
    asm("cvt.rna.tf32.f32 %0, %1;" : "=r"(u) : "f"(x));
    return __uint_as_float(u);
}
__device__ __forceinline__ uint32_t smem_u32(const void* p) {
    uint32_t a;
    asm("{ .reg .u64 t; cvta.to.shared.u64 t, %1; cvt.u32.u64 %0, t; }"
        : "=r"(a) : "l"(p));
    return a;
}
#define CPA16(saddr, gptr) \
    asm volatile("cp.async.cg.shared.global [%0], [%1], 16;" \
                 :: "r"(saddr), "l"(gptr) : "memory")
#define CP_COMMIT() asm volatile("cp.async.commit_group;" ::: "memory")
#define CP_WAIT1()  asm volatile("cp.async.wait_group 1;"  ::: "memory")

#define LDSM4(r0, r1, r2, r3, addr) \
    asm volatile("ldmatrix.sync.aligned.m8n8.x4.shared.b16 {%0,%1,%2,%3}, [%4];" \
                 : "=r"(r0), "=r"(r1), "=r"(r2), "=r"(r3) : "r"(addr))

__device__ __forceinline__ void mma8(float* d, const uint32_t* a, const uint32_t* b) {
    asm volatile(
        "mma.sync.aligned.m16n8k8.row.col.f32.tf32.tf32.f32 "
        "{%0,%1,%2,%3}, {%4,%5,%6,%7}, {%8,%9}, {%0,%1,%2,%3};"
        : "+f"(d[0]), "+f"(d[1]), "+f"(d[2]), "+f"(d[3])
        : "r"(a[0]), "r"(a[1]), "r"(a[2]), "r"(a[3]), "r"(b[0]), "r"(b[1]));
}

// ---------------- prep kernels ----------------

__global__ void blkmap_k(const int* __restrict__ idxw) {
    int t = threadIdx.x;
    if (t < 256) g_blkmap[t] = -1;
    __syncthreads();
    if (t == 0) {
        bool is64 = true;
        for (int i = 0; i < 32; i++)
            if (idxw[2 * i + 1] != 0) { is64 = false; break; }
        for (int b = 0; b < 32; b++) {
            int ro, ci;
            if (is64) {
                const long long* q = (const long long*)idxw;
                ro = (int)q[2 * b]; ci = (int)q[2 * b + 1];
            } else {
                ro = idxw[2 * b]; ci = idxw[2 * b + 1];
            }
            if (ro >= 0 && ro < 16 && ci >= 0 && ci < 16)
                g_blkmap[ro * 16 + ci] = b;
        }
    }
}

__global__ void prep_w_k(const float* __restrict__ w, const float* __restrict__ sel) {
    int gi = blockIdx.x * 256 + threadIdx.x;
    int o  = gi >> 10;
    int i  = (gi & 1023) << 2;
    int blk = g_blkmap[((o >> 8) << 4) + (i >> 8)];
    float4 v;
    if (blk >= 0)
        v = *(const float4*)(sel + (((size_t)blk << 8) + (o & 255)) * 256 + (i & 255));
    else
        v = ((const float4*)w)[gi];
    v.x = tf32_rn(v.x); v.y = tf32_rn(v.y); v.z = tf32_rn(v.z); v.w = tf32_rn(v.w);
    ((float4*)g_W)[gi] = v;
}

__global__ void prep_x_k(const float* __restrict__ x) {
    int gi = blockIdx.x * 256 + threadIdx.x;
    float4 v = ((const float4*)x)[gi];
    v.x = tf32_rn(v.x); v.y = tf32_rn(v.y); v.z = tf32_rn(v.z); v.w = tf32_rn(v.w);
    ((float4*)g_X)[gi] = v;
}

// ---------------- GEMM ----------------
#define LDSROW       36
#define HALF_BYTES   (128 * LDSROW * 4)        // 18432
#define STAGE_BYTES_ (2 * HALF_BYTES)          // 36864
#define NSTAGES      3
#define SMEM_BYTES   (NSTAGES * STAGE_BYTES_)  // 110592

__global__ void __launch_bounds__(128, 2)
LinearLayer_MatrixSparsity_9801115369812_kernel(float* __restrict__ out) {
    extern __shared__ float smem[];
    const uint32_t sb = smem_u32(smem);
    const int tid  = threadIdx.x;
    const int lane = tid & 31;
    const int wid  = tid >> 5;           // 0..3
    const int tile_n = blockIdx.x;       // 0..31
    const int tile_m = blockIdx.y;       // 0..63

    // ---- loader mapping ----
    const float* ga = g_X + (size_t)(tile_m * 128 + (tid >> 3)) * 4096 + (tid & 7) * 4;
    const float* gb = g_W + (size_t)(tile_n * 128 + (tid >> 3)) * 4096 + (tid & 7) * 4;
    const uint32_t soA = sb + (uint32_t)((tid >> 3) * (LDSROW * 4) + (tid & 7) * 16);
    const uint32_t soB = soA + HALF_BYTES;

    // one A-row + one B-row pair of cp.asyncs
    #define CPA_PAIR(j, _d, _k)                                                   \
        CPA16(soA + (_d) + (j) * (16 * LDSROW * 4), ga + (size_t)(j) * (16 * 4096) + (_k)); \
        CPA16(soB + (_d) + (j) * (16 * LDSROW * 4), gb + (size_t)(j) * (16 * 4096) + (_k))

    #define LOAD_STAGE(s, kc) do {                                                \
        const uint32_t _d = (uint32_t)(s) * STAGE_BYTES_;                         \
        const int _k = (kc) * 32;                                                 \
        _Pragma("unroll")                                                         \
        for (int j = 0; j < 8; j++) { CPA_PAIR(j, _d, _k); }                      \
    } while (0)

    LOAD_STAGE(0, 0); CP_COMMIT();
    LOAD_STAGE(1, 1); CP_COMMIT();

    const int warp_m = (wid >> 1) * 64;
    const int warp_n = (wid & 1) * 64;

    // ldmatrix per-thread offsets (identical mapping to the passing R6 kernel)
    uint32_t aoff[4], boff[4];
    {
        const int r8a = (lane >> 3) & 1, c4a = (lane >> 4) & 1;
        #pragma unroll
        for (int mi = 0; mi < 4; mi++)
            aoff[mi] = (uint32_t)((warp_m + mi * 16 + (lane & 7) + r8a * 8) * (LDSROW * 4)
                                  + c4a * 16);
        const int r8b = (lane >> 4) & 1, c4b = (lane >> 3) & 1;
        #pragma unroll
        for (int nj = 0; nj < 4; nj++)
            boff[nj] = (uint32_t)(HALF_BYTES
                                  + (warp_n + nj * 16 + (lane & 7) + r8b * 8) * (LDSROW * 4)
                                  + c4b * 16);
    }

    float acc[4][8][4];
    #pragma unroll
    for (int mi = 0; mi < 4; mi++)
        #pragma unroll
        for (int ni = 0; ni < 8; ni++)
            #pragma unroll
            for (int q = 0; q < 4; q++) acc[mi][ni][q] = 0.0f;

    // double-buffered fragments
    uint32_t af[2][4][4], bf[2][4][4];

    #define LDSM_KS(buf, koff) do {                                               \
        _Pragma("unroll")                                                         \
        for (int nj = 0; nj < 4; nj++)                                            \
            LDSM4(bf[buf][nj][0], bf[buf][nj][1], bf[buf][nj][2], bf[buf][nj][3], \
                  sbase + boff[nj] + (koff));                                     \
        _Pragma("unroll")                                                         \
        for (int mi = 0; mi < 4; mi++)                                            \
            LDSM4(af[buf][mi][0], af[buf][mi][1], af[buf][mi][2], af[buf][mi][3], \
                  sbase + aoff[mi] + (koff));                                     \
    } while (0)

    int cs = 0, ls = 2;
    for (int kc = 0; kc < 128; kc++) {
        CP_WAIT1();
        __syncthreads();
        const uint32_t sbase = sb + (uint32_t)cs * STAGE_BYTES_;
        const uint32_t ld    = (uint32_t)ls * STAGE_BYTES_;
        const int      lk    = (kc + 2) * 32;
        const bool     doload = (kc + 2 < 128);

        LDSM_KS(0, 0);                        // preload ks0 fragments
        #pragma unroll
        for (int ks = 0; ks < 4; ks++) {
            if (ks < 3) LDSM_KS((ks + 1) & 1, (uint32_t)((ks + 1) * 32));  // prefetch ks+1
            if (doload) {                     // 4 cp.asyncs folded into mma stream
                CPA_PAIR(2 * ks,     ld, lk);
                CPA_PAIR(2 * ks + 1, ld, lk);
            }
            const int b = ks & 1;
            #pragma unroll
            for (int mi = 0; mi < 4; mi++)
                #pragma unroll
                for (int ni = 0; ni < 8; ni++)
                    mma8(acc[mi][ni], af[b][mi], &bf[b][ni >> 1][(ni & 1) * 2]);
        }
        CP_COMMIT();                          // one group per iteration (even if empty)
        cs = (cs == NSTAGES - 1) ? 0 : cs + 1;
        ls = (ls == NSTAGES - 1) ? 0 : ls + 1;
    }

    // ---- epilogue ----
    const int qid = lane & 3;
    const int gid = lane >> 2;
    #pragma unroll
    for (int mi = 0; mi < 4; mi++) {
        #pragma unroll
        for (int ni = 0; ni < 8; ni++) {
            const size_t r0 = (size_t)(tile_m * 128 + warp_m + mi * 16 + gid);
            const int    c  = tile_n * 128 + warp_n + ni * 8 + qid * 2;
            *(float2*)(out + r0 * 4096 + c) =
                make_float2(acc[mi][ni][0], acc[mi][ni][1]);
            *(float2*)(out + (r0 + 8) * 4096 + c) =
                make_float2(acc[mi][ni][2], acc[mi][ni][3]);
        }
    }
}

// ---------------- launch ----------------
extern "C" void kernel_launch(void* const* d_in, const int* in_sizes, int n_in,
                              void* d_out, int out_size) {
    const float* x   = nullptr;
    const float* sel = nullptr;
    const float* w   = nullptr;
    const int*   idx = nullptr;
    for (int i = 0; i < n_in; i++) {
        switch (in_sizes[i]) {
            case 33554432: x   = (const float*)d_in[i]; break;
            case 16777216: w   = (const float*)d_in[i]; break;
            case 2097152:  sel = (const float*)d_in[i]; break;
            default:       idx = (const int*)d_in[i];   break;
        }
    }
    if (!x)   x   = (const float*)d_in[0];
    if (!sel) sel = (const float*)d_in[1];
    if (!w)   w   = (const float*)d_in[2];
    if (!idx) idx = (const int*)d_in[3];

    cudaFuncSetAttribute(LinearLayer_MatrixSparsity_9801115369812_kernel,
                         cudaFuncAttributeMaxDynamicSharedMemorySize, SMEM_BYTES);

    blkmap_k<<<1, 256>>>(idx);
    prep_w_k<<<16384, 256>>>(w, sel);
    prep_x_k<<<32768, 256>>>(x);
    LinearLayer_MatrixSparsity_9801115369812_kernel
        <<<dim3(32, 64), 128, SMEM_BYTES>>>((float*)d_out);
}

// round 8
// speedup vs baseline: 1.7702x; 1.0746x over previous
#include <cuda_runtime.h>
#include <cstdint>

// ============================================================================
// y = x @ scatter(W, sel, idx)^T      (M=8192, N=4096, K=4096, f32)
//
// Baseline-PTX tensor path (tcgen05 not available under compute_103):
//   prep: round x / scattered W to tf32 (cvt.rna) into device scratch
//         (single fused kernel: W-blocks + X-blocks run concurrently)
//   GEMM: cp.async 3-stage pipeline + mma.sync m16n8k8 tf32
//         CTA 128x128, BK=32, 4 warps (warp tile 64x64), 2 CTAs/SM
//         mid-chunk barrier: CP_WAIT+bar between ks2 and ks3, ks3 prefetches
//         NEXT chunk's ks0 fragments -> tensor pipe never drains at the
//         chunk boundary.
// ============================================================================

// ---------------- device-global scratch (sanctioned) ----------------
__device__ float g_X[33554432];   // 8192 x 4096 tf32-rounded
__device__ float g_W[16777216];   // 4096 x 4096 scattered + tf32-rounded
__device__ int   g_blkmap[256];   // 16x16 grid -> block id or -1

// ---------------- helpers ----------------
__device__ __forceinline__ float tf32_rn(float x) {
    uint32_t u;
    asm("cvt.rna.tf32.f32 %0, %1;" : "=r"(u) : "f"(x));
    return __uint_as_float(u);
}
__device__ __forceinline__ uint32_t smem_u32(const void* p) {
    uint32_t a;
    asm("{ .reg .u64 t; cvta.to.shared.u64 t, %1; cvt.u32.u64 %0, t; }"
        : "=r"(a) : "l"(p));
    return a;
}
#define CPA16(saddr, gptr) \
    asm volatile("cp.async.cg.shared.global [%0], [%1], 16;" \
                 :: "r"(saddr), "l"(gptr) : "memory")
#define CP_COMMIT() asm volatile("cp.async.commit_group;" ::: "memory")
#define CP_WAIT1()  asm volatile("cp.async.wait_group 1;"  ::: "memory")

#define LDSM4(r0, r1, r2, r3, addr) \
    asm volatile("ldmatrix.sync.aligned.m8n8.x4.shared.b16 {%0,%1,%2,%3}, [%4];" \
                 : "=r"(r0), "=r"(r1), "=r"(r2), "=r"(r3) : "r"(addr))

__device__ __forceinline__ void mma8(float* d, const uint32_t* a, const uint32_t* b) {
    asm volatile(
        "mma.sync.aligned.m16n8k8.row.col.f32.tf32.tf32.f32 "
        "{%0,%1,%2,%3}, {%4,%5,%6,%7}, {%8,%9}, {%0,%1,%2,%3};"
        : "+f"(d[0]), "+f"(d[1]), "+f"(d[2]), "+f"(d[3])
        : "r"(a[0]), "r"(a[1]), "r"(a[2]), "r"(a[3]), "r"(b[0]), "r"(b[1]));
}

// ---------------- prep kernels ----------------

__global__ void blkmap_k(const int* __restrict__ idxw) {
    int t = threadIdx.x;
    if (t < 256) g_blkmap[t] = -1;
    __syncthreads();
    if (t == 0) {
        bool is64 = true;
        for (int i = 0; i < 32; i++)
            if (idxw[2 * i + 1] != 0) { is64 = false; break; }
        for (int b = 0; b < 32; b++) {
            int ro, ci;
            if (is64) {
                const long long* q = (const long long*)idxw;
                ro = (int)q[2 * b]; ci = (int)q[2 * b + 1];
            } else {
                ro = idxw[2 * b]; ci = idxw[2 * b + 1];
            }
            if (ro >= 0 && ro < 16 && ci >= 0 && ci < 16)
                g_blkmap[ro * 16 + ci] = b;
        }
    }
}

// Fused prep: blocks [0,16384) scatter+round W; blocks [16384,49152) round X.
__global__ void prep_xw_k(const float* __restrict__ x,
                          const float* __restrict__ w,
                          const float* __restrict__ sel) {
    const int bid = blockIdx.x;
    if (bid < 16384) {
        int gi = bid * 256 + threadIdx.x;      // float4 index into W
        int o  = gi >> 10;
        int i  = (gi & 1023) << 2;
        int blk = g_blkmap[((o >> 8) << 4) + (i >> 8)];
        float4 v;
        if (blk >= 0)
            v = *(const float4*)(sel + (((size_t)blk << 8) + (o & 255)) * 256 + (i & 255));
        else
            v = ((const float4*)w)[gi];
        v.x = tf32_rn(v.x); v.y = tf32_rn(v.y); v.z = tf32_rn(v.z); v.w = tf32_rn(v.w);
        ((float4*)g_W)[gi] = v;
    } else {
        int gi = (bid - 16384) * 256 + threadIdx.x;   // float4 index into X
        float4 v = ((const float4*)x)[gi];
        v.x = tf32_rn(v.x); v.y = tf32_rn(v.y); v.z = tf32_rn(v.z); v.w = tf32_rn(v.w);
        ((float4*)g_X)[gi] = v;
    }
}

// ---------------- GEMM ----------------
#define LDSROW       36
#define HALF_BYTES   (128 * LDSROW * 4)        // 18432
#define STAGE_BYTES_ (2 * HALF_BYTES)          // 36864
#define NSTAGES      3
#define SMEM_BYTES   (NSTAGES * STAGE_BYTES_)  // 110592

__global__ void __launch_bounds__(128, 2)
LinearLayer_MatrixSparsity_9801115369812_kernel(float* __restrict__ out) {
    extern __shared__ float smem[];
    const uint32_t sb = smem_u32(smem);
    const int tid  = threadIdx.x;
    const int lane = tid & 31;
    const int wid  = tid >> 5;           // 0..3
    const int tile_n = blockIdx.x;       // 0..31
    const int tile_m = blockIdx.y;       // 0..63

    // ---- loader mapping ----
    const float* ga = g_X + (size_t)(tile_m * 128 + (tid >> 3)) * 4096 + (tid & 7) * 4;
    const float* gb = g_W + (size_t)(tile_n * 128 + (tid >> 3)) * 4096 + (tid & 7) * 4;
    const uint32_t soA = sb + (uint32_t)((tid >> 3) * (LDSROW * 4) + (tid & 7) * 16);
    const uint32_t soB = soA + HALF_BYTES;

    #define CPA_PAIR(j, _d, _k)                                                   \
        CPA16(soA + (_d) + (j) * (16 * LDSROW * 4), ga + (size_t)(j) * (16 * 4096) + (_k)); \
        CPA16(soB + (_d) + (j) * (16 * LDSROW * 4), gb + (size_t)(j) * (16 * 4096) + (_k))

    #define LOAD_STAGE(s, kc) do {                                               \
        const uint32_t _d = (uint32_t)(s) * STAGE_BYTES_;                        \
        const int _k = (kc) * 32;                                                \
        _Pragma("unroll")                                                        \
        for (int j = 0; j < 8; j++) { CPA_PAIR(j, _d, _k); }                     \
    } while (0)

    LOAD_STAGE(0, 0); CP_COMMIT();
    LOAD_STAGE(1, 1); CP_COMMIT();

    const int warp_m = (wid >> 1) * 64;
    const int warp_n = (wid & 1) * 64;

    // ldmatrix per-thread offsets (same mapping as passing R6/R7 kernels)
    uint32_t aoff[4], boff[4];
    {
        const int r8a = (lane >> 3) & 1, c4a = (lane >> 4) & 1;
        #pragma unroll
        for (int mi = 0; mi < 4; mi++)
            aoff[mi] = (uint32_t)((warp_m + mi * 16 + (lane & 7) + r8a * 8) * (LDSROW * 4)
                                  + c4a * 16);
        const int r8b = (lane >> 4) & 1, c4b = (lane >> 3) & 1;
        #pragma unroll
        for (int nj = 0; nj < 4; nj++)
            boff[nj] = (uint32_t)(HALF_BYTES
                                  + (warp_n + nj * 16 + (lane & 7) + r8b * 8) * (LDSROW * 4)
                                  + c4b * 16);
    }

    float acc[4][8][4];
    #pragma unroll
    for (int mi = 0; mi < 4; mi++)
        #pragma unroll
        for (int ni = 0; ni < 8; ni++)
            #pragma unroll
            for (int q = 0; q < 4; q++) acc[mi][ni][q] = 0.0f;

    uint32_t af[2][4][4], bf[2][4][4];

    #define LDSM_KS(buf, base, koff) do {                                         \
        _Pragma("unroll")                                                         \
        for (int nj = 0; nj < 4; nj++)                                            \
            LDSM4(bf[buf][nj][0], bf[buf][nj][1], bf[buf][nj][2], bf[buf][nj][3], \
                  (base) + boff[nj] + (koff));                                    \
        _Pragma("unroll")                                                         \
        for (int mi = 0; mi < 4; mi++)                                            \
            LDSM4(af[buf][mi][0], af[buf][mi][1], af[buf][mi][2], af[buf][mi][3], \
                  (base) + aoff[mi] + (koff));                                    \
    } while (0)

    #define MMA_KS(buf) do {                                                      \
        _Pragma("unroll")                                                         \
        for (int mi = 0; mi < 4; mi++)                                            \
            _Pragma("unroll")                                                     \
            for (int ni = 0; ni < 8; ni++)                                        \
                mma8(acc[mi][ni], af[buf][mi], &bf[buf][ni >> 1][(ni & 1) * 2]);  \
    } while (0)

    // prologue: chunk 0 resident + ks0 fragments preloaded
    CP_WAIT1();
    __syncthreads();
    LDSM_KS(0, sb, 0);

    int cs = 0, ls = 2;
    for (int kc = 0; kc < 128; kc++) {
        const uint32_t sbase = sb + (uint32_t)cs * STAGE_BYTES_;
        const uint32_t nbase = sb + (uint32_t)((cs == NSTAGES - 1) ? 0 : cs + 1) * STAGE_BYTES_;
        const uint32_t ld    = (uint32_t)ls * STAGE_BYTES_;
        const int      lk    = (kc + 2) * 32;
        const bool     doload = (kc + 2 < 128);

        // ks0: prefetch ks1 frags, 3 cp.async pairs, mma(buf0)
        LDSM_KS(1, sbase, 32);
        if (doload) { CPA_PAIR(0, ld, lk); CPA_PAIR(1, ld, lk); CPA_PAIR(2, ld, lk); }
        MMA_KS(0);
        // ks1: prefetch ks2 frags, 3 pairs, mma(buf1)
        LDSM_KS(0, sbase, 64);
        if (doload) { CPA_PAIR(3, ld, lk); CPA_PAIR(4, ld, lk); CPA_PAIR(5, ld, lk); }
        MMA_KS(1);
        // ks2: prefetch ks3 frags, last 2 pairs, commit, mma(buf0)
        LDSM_KS(1, sbase, 96);
        if (doload) { CPA_PAIR(6, ld, lk); CPA_PAIR(7, ld, lk); }
        CP_COMMIT();
        MMA_KS(0);
        // mid-chunk sync: chunk kc+1 now complete (pending group = kc+2);
        // all reads of stage cs done (ks3 frags already in regs)
        CP_WAIT1();
        __syncthreads();
        // ks3: prefetch NEXT chunk's ks0 frags from nbase, mma(buf1)
        LDSM_KS(0, nbase, 0);
        MMA_KS(1);

        cs = (cs == NSTAGES - 1) ? 0 : cs + 1;
        ls = (ls == NSTAGES - 1) ? 0 : ls + 1;
    }

    // ---- epilogue ----
    const int qid = lane & 3;
    const int gid = lane >> 2;
    #pragma unroll
    for (int mi = 0; mi < 4; mi++) {
        #pragma unroll
        for (int ni = 0; ni < 8; ni++) {
            const size_t r0 = (size_t)(tile_m * 128 + warp_m + mi * 16 + gid);
            const int    c  = tile_n * 128 + warp_n + ni * 8 + qid * 2;
            *(float2*)(out + r0 * 4096 + c) =
                make_float2(acc[mi][ni][0], acc[mi][ni][1]);
            *(float2*)(out + (r0 + 8) * 4096 + c) =
                make_float2(acc[mi][ni][2], acc[mi][ni][3]);
        }
    }
}

// ---------------- launch ----------------
extern "C" void kernel_launch(void* const* d_in, const int* in_sizes, int n_in,
                              void* d_out, int out_size) {
    const float* x   = nullptr;
    const float* sel = nullptr;
    const float* w   = nullptr;
    const int*   idx = nullptr;
    for (int i = 0; i < n_in; i++) {
        switch (in_sizes[i]) {
            case 33554432: x   = (const float*)d_in[i]; break;
            case 16777216: w   = (const float*)d_in[i]; break;
            case 2097152:  sel = (const float*)d_in[i]; break;
            default:       idx = (const int*)d_in[i];   break;
        }
    }
    if (!x)   x   = (const float*)d_in[0];
    if (!sel) sel = (const float*)d_in[1];
    if (!w)   w   = (const float*)d_in[2];
    if (!idx) idx = (const int*)d_in[3];

    cudaFuncSetAttribute(LinearLayer_MatrixSparsity_9801115369812_kernel,
                         cudaFuncAttributeMaxDynamicSharedMemorySize, SMEM_BYTES);

    blkmap_k<<<1, 256>>>(idx);
    prep_xw_k<<<49152, 256>>>(x, w, sel);
    LinearLayer_MatrixSparsity_9801115369812_kernel
        <<<dim3(32, 64), 128, SMEM_BYTES>>>((float*)d_out);
}